// round 2
// baseline (speedup 1.0000x reference)
#include <cuda_runtime.h>
#include <cuda_bf16.h>

// LoongSpike fractional-SSM Vandermonde kernel, round 2.
// K[h,l] = 2*Re( sum_n C_disc[h,n] * exp(dtA[h,n])^l ), geometric recurrence.
// Round-2 changes: (1) packed f32x2 FFMA2 mainloop (states packed in pairs),
// (2) LCc 32->16 doubling warp count for latency hiding.

#define Hh      512
#define NSTc    32
#define LCc     16      // l-elements per thread
#define CPBc    32      // chunks per block -> block covers 512 l
#define NSTATES 64      // M*NST complex states
#define GRPS    8       // groups of 8 states (= 4 packed pairs)
#define GS      8

typedef unsigned long long u64;

#define MUL2(d, a, b) \
    asm("mul.rn.f32x2 %0, %1, %2;" : "=l"(d) : "l"(a), "l"(b))
#define ADD2(d, a, b) \
    asm("add.rn.f32x2 %0, %1, %2;" : "=l"(d) : "l"(a), "l"(b))
#define FMA2(d, a, b, c) \
    asm("fma.rn.f32x2 %0, %1, %2, %3;" : "=l"(d) : "l"(a), "l"(b), "l"(c))
#define PACK2(d, lo, hi) \
    asm("mov.b64 %0, {%1, %2};" : "=l"(d) : "r"(__float_as_uint(lo)), "r"(__float_as_uint(hi)))
#define UNPACK2(lo, hi, v) \
    asm("mov.b64 {%0, %1}, %2;" : "=r"(lo), "=r"(hi) : "l"(v))

__global__ __launch_bounds__(32) void loong_spike_kernel(
    const float* __restrict__ C_real,      // [1, H, NST, 2]
    const float* __restrict__ log_dt,      // [H]
    const float* __restrict__ log_A_real,  // [H, NST]
    const float* __restrict__ A_imag,      // [H, NST]
    const float* __restrict__ omega_logit, // [2]
    const float* __restrict__ eta_logit,   // [2]
    float* __restrict__ out,               // [1, H, L]
    int L)
{
    __shared__ float2 W0[NSTATES][CPBc + 1];  // chunk-start values, padded pitch
    __shared__ float2 Rs[NSTATES];            // per-state step ratio r = exp(dtA)

    const int tid = threadIdx.x;              // 0..31
    const int h   = blockIdx.y;
    const int bx  = blockIdx.x;
    const int l0_base = bx * (CPBc * LCc);

    // ---------------- Phase 1: per-state setup + chunk-start table ---------
    const float dt = expf(log_dt[h]);
    #pragma unroll
    for (int s = 0; s < 2; ++s) {
        const int nst = tid;
        const int n   = s * NSTc + tid;       // n = m*NST + nst

        const float Are = -expf(log_A_real[h * NSTc + nst]);
        const float Aim = A_imag[h * NSTc + nst];

        const float ol = omega_logit[s];
        const float el = eta_logit[s];
        const float omega = 1e-6f + (1.0f / (1.0f + expf(-ol))) * (100.0f - 1e-6f);
        const float eta   = 1e-6f + (1.0f / (1.0f + expf(-el))) * (10.0f  - 1e-6f);

        const float Afr = -omega + eta * Are;     // A_frac (complex)
        const float Afi = eta * Aim;
        const float Cre = eta * C_real[(h * NSTc + nst) * 2 + 0];  // C_frac
        const float Cim = eta * C_real[(h * NSTc + nst) * 2 + 1];

        const float dr = Afr * dt;                // dtA
        const float di = Afi * dt;

        // r = exp(dtA)  (also exp_dtA for the discretization)
        float er, sn, cs;
        er = expf(dr);
        sincosf(di, &sn, &cs);
        const float rre = er * cs;
        const float rim = er * sn;

        // C_disc = C_frac * (exp_dtA - 1) / (A_frac + 1e-8)   (or * dt if tiny)
        float Cdre, Cdim;
        const float mag2 = Afr * Afr + Afi * Afi;
        if (mag2 < 1e-12f) {
            Cdre = Cre * dt;
            Cdim = Cim * dt;
        } else {
            const float nre = rre - 1.0f, nim = rim;
            const float tre = Cre * nre - Cim * nim;
            const float tim = Cre * nim + Cim * nre;
            const float dre = Afr + 1e-8f, dim = Afi;
            const float inv = 1.0f / (dre * dre + dim * dim);
            Cdre = (tre * dre + tim * dim) * inv;
            Cdim = (tim * dre - tre * dim) * inv;
        }

        // chunk-start value at l0_base: w = C_disc * exp(dtA * l0_base)
        const float p = (float)l0_base;
        float ssn, scs;
        const float serx = expf(dr * p);
        sincosf(di * p, &ssn, &scs);
        const float Sre = serx * scs, Sim = serx * ssn;
        float wre = Cdre * Sre - Cdim * Sim;
        float wim = Cdre * Sim + Cdim * Sre;

        // per-chunk advance R = exp(dtA * LCc)
        float sL, cL;
        const float erL = expf(dr * (float)LCc);
        sincosf(di * (float)LCc, &sL, &cL);
        const float Rre = erL * cL, Rim = erL * sL;

        Rs[n] = make_float2(rre, rim);
        #pragma unroll 1
        for (int ci = 0; ci < CPBc; ++ci) {
            W0[n][ci] = make_float2(wre, wim);
            const float t1 = wre * Rre - wim * Rim;
            const float t2 = wre * Rim + wim * Rre;
            wre = t1; wim = t2;
        }
    }
    __syncthreads();

    // ---------------- Phase 2: packed f32x2 recurrence sweep ----------------
    const int ci = tid;
    const int l0 = l0_base + ci * LCc;
    if (l0 >= L) return;

    u64 acc2[LCc];
    #pragma unroll
    for (int l = 0; l < LCc; ++l) acc2[l] = 0ull;

    #pragma unroll 1
    for (int g = 0; g < GRPS; ++g) {
        // 8 states as 4 packed pairs
        u64 wr2[4], wi2[4], rr2[4], ri2[4], nri2[4];
        #pragma unroll
        for (int p = 0; p < 4; ++p) {
            const int n0 = g * GS + 2 * p;
            const float2 wa = W0[n0][ci];
            const float2 wb = W0[n0 + 1][ci];
            const float2 ra = Rs[n0];
            const float2 rb = Rs[n0 + 1];
            PACK2(wr2[p], wa.x, wb.x);
            PACK2(wi2[p], wa.y, wb.y);
            PACK2(rr2[p], ra.x, rb.x);
            PACK2(ri2[p], ra.y, rb.y);
            PACK2(nri2[p], -ra.y, -rb.y);
        }
        #pragma unroll
        for (int l = 0; l < LCc; ++l) {
            #pragma unroll
            for (int p = 0; p < 4; ++p) {
                ADD2(acc2[l], acc2[l], wr2[p]);          // accumulate Re (both lanes)
                u64 t, u, nw, nv;
                MUL2(t, wi2[p], nri2[p]);                // -wi*ri
                FMA2(nw, wr2[p], rr2[p], t);             // wr' = wr*rr - wi*ri
                MUL2(u, wi2[p], rr2[p]);                 //  wi*rr
                FMA2(nv, wr2[p], ri2[p], u);             // wi' = wr*ri + wi*rr
                wr2[p] = nw; wi2[p] = nv;
            }
        }
    }

    float* op = out + (size_t)h * L + l0;
    if (l0 + LCc <= L) {
        float res[LCc];
        #pragma unroll
        for (int l = 0; l < LCc; ++l) {
            unsigned int lo, hi;
            UNPACK2(lo, hi, acc2[l]);
            res[l] = 2.0f * (__uint_as_float(lo) + __uint_as_float(hi));
        }
        #pragma unroll
        for (int l = 0; l < LCc; l += 4) {
            *reinterpret_cast<float4*>(op + l) =
                make_float4(res[l], res[l + 1], res[l + 2], res[l + 3]);
        }
    } else {
        for (int l = 0; l < LCc && l0 + l < L; ++l) {
            unsigned int lo, hi;
            UNPACK2(lo, hi, acc2[l]);
            op[l] = 2.0f * (__uint_as_float(lo) + __uint_as_float(hi));
        }
    }
}

extern "C" void kernel_launch(void* const* d_in, const int* in_sizes, int n_in,
                              void* d_out, int out_size) {
    const float* C_real      = (const float*)d_in[0];
    const float* log_dt      = (const float*)d_in[1];
    const float* log_A_real  = (const float*)d_in[2];
    const float* A_imag      = (const float*)d_in[3];
    const float* omega_logit = (const float*)d_in[4];
    const float* eta_logit   = (const float*)d_in[5];
    float* out = (float*)d_out;

    const int L  = out_size / Hh;                 // CH == 1
    const int Lc = (L + LCc - 1) / LCc;           // total chunks
    const int gx = (Lc + CPBc - 1) / CPBc;        // blocks along l

    dim3 grid(gx, Hh);
    loong_spike_kernel<<<grid, 32>>>(C_real, log_dt, log_A_real, A_imag,
                                     omega_logit, eta_logit, out, L);
}

// round 3
// speedup vs baseline: 1.4839x; 1.4839x over previous
#include <cuda_runtime.h>
#include <cuda_bf16.h>

// LoongSpike fractional-SSM Vandermonde kernel, round 3.
// K[h,l] = 2*Re( sum_n C_disc[h,n] * r_n^l ),  r_n = exp(dtA[h,n]).
// Round-3: per-state REAL second-order recurrence
//    x_{l+1} = 2Re(r) x_l - |r|^2 x_{l-1},   x_l = Re(w r^l)
// packed two-states-per-f32x2 -> 3 packed ops per 2 states per l.
// Geometry identical to round 1 (best measured): 1024 blocks x 32 thr.

#define Hh      512
#define NSTc    32
#define LCc     32      // l-elements per thread
#define CPBc    32      // chunks per block -> block covers 1024 l
#define NSTATES 64
#define GRPS    8       // 8 groups x 4 packed pairs = 32 pairs = 64 states
#define NPAIR   4

typedef unsigned long long u64;

#define MUL2(d, a, b) \
    asm("mul.rn.f32x2 %0, %1, %2;" : "=l"(d) : "l"(a), "l"(b))
#define ADD2(d, a, b) \
    asm("add.rn.f32x2 %0, %1, %2;" : "=l"(d) : "l"(a), "l"(b))
#define FMA2(d, a, b, c) \
    asm("fma.rn.f32x2 %0, %1, %2, %3;" : "=l"(d) : "l"(a), "l"(b), "l"(c))
#define PACK2(d, lo, hi) \
    asm("mov.b64 %0, {%1, %2};" : "=l"(d) : "r"(__float_as_uint(lo)), "r"(__float_as_uint(hi)))
#define UNPACK2(lo, hi, v) \
    asm("mov.b64 {%0, %1}, %2;" : "=r"(lo), "=r"(hi) : "l"(v))

__global__ __launch_bounds__(32) void loong_spike_kernel(
    const float* __restrict__ C_real,      // [1, H, NST, 2]
    const float* __restrict__ log_dt,      // [H]
    const float* __restrict__ log_A_real,  // [H, NST]
    const float* __restrict__ A_imag,      // [H, NST]
    const float* __restrict__ omega_logit, // [2]
    const float* __restrict__ eta_logit,   // [2]
    float* __restrict__ out,               // [1, H, L]
    int L)
{
    __shared__ float2 W0[NSTATES][CPBc + 1];  // chunk-start complex w, padded pitch
    __shared__ float2 Rs[NSTATES];            // per-state ratio r = exp(dtA)

    const int tid = threadIdx.x;              // 0..31
    const int h   = blockIdx.y;
    const int bx  = blockIdx.x;
    const int l0_base = bx * (CPBc * LCc);

    // ---------------- Phase 1: per-state setup + chunk-start table ---------
    const float dt = expf(log_dt[h]);
    #pragma unroll
    for (int s = 0; s < 2; ++s) {
        const int nst = tid;
        const int n   = s * NSTc + tid;       // n = m*NST + nst

        const float Are = -expf(log_A_real[h * NSTc + nst]);
        const float Aim = A_imag[h * NSTc + nst];

        const float ol = omega_logit[s];
        const float el = eta_logit[s];
        const float omega = 1e-6f + (1.0f / (1.0f + expf(-ol))) * (100.0f - 1e-6f);
        const float eta   = 1e-6f + (1.0f / (1.0f + expf(-el))) * (10.0f  - 1e-6f);

        const float Afr = -omega + eta * Are;     // A_frac
        const float Afi = eta * Aim;
        const float Cre = eta * C_real[(h * NSTc + nst) * 2 + 0];  // C_frac
        const float Cim = eta * C_real[(h * NSTc + nst) * 2 + 1];

        const float dr = Afr * dt;                // dtA
        const float di = Afi * dt;

        float er, sn, cs;
        er = expf(dr);
        sincosf(di, &sn, &cs);
        const float rre = er * cs;
        const float rim = er * sn;

        // C_disc = C_frac * (exp_dtA - 1) / (A_frac + 1e-8)   (or * dt if tiny)
        float Cdre, Cdim;
        const float mag2 = Afr * Afr + Afi * Afi;
        if (mag2 < 1e-12f) {
            Cdre = Cre * dt;
            Cdim = Cim * dt;
        } else {
            const float nre = rre - 1.0f, nim = rim;
            const float tre = Cre * nre - Cim * nim;
            const float tim = Cre * nim + Cim * nre;
            const float dre = Afr + 1e-8f, dim = Afi;
            const float inv = 1.0f / (dre * dre + dim * dim);
            Cdre = (tre * dre + tim * dim) * inv;
            Cdim = (tim * dre - tre * dim) * inv;
        }

        // chunk-start value at l0_base: w = C_disc * exp(dtA * l0_base)
        const float p = (float)l0_base;
        float ssn, scs;
        const float serx = expf(dr * p);
        sincosf(di * p, &ssn, &scs);
        const float Sre = serx * scs, Sim = serx * ssn;
        float wre = Cdre * Sre - Cdim * Sim;
        float wim = Cdre * Sim + Cdim * Sre;

        // per-chunk advance R = exp(dtA * LCc)
        float sL, cL;
        const float erL = expf(dr * (float)LCc);
        sincosf(di * (float)LCc, &sL, &cL);
        const float Rre = erL * cL, Rim = erL * sL;

        Rs[n] = make_float2(rre, rim);
        #pragma unroll 1
        for (int ci = 0; ci < CPBc; ++ci) {
            W0[n][ci] = make_float2(wre, wim);
            const float t1 = wre * Rre - wim * Rim;
            const float t2 = wre * Rim + wim * Rre;
            wre = t1; wim = t2;
        }
    }
    __syncthreads();

    // ---------------- Phase 2: packed real second-order recurrence ---------
    const int ci = tid;
    const int l0 = l0_base + ci * LCc;
    if (l0 >= L) return;

    u64 acc2[LCc];
    #pragma unroll
    for (int l = 0; l < LCc; ++l) acc2[l] = 0ull;

    #pragma unroll 1
    for (int g = 0; g < GRPS; ++g) {
        u64 prev2[NPAIR], cur2[NPAIR], p2[NPAIR], q2[NPAIR];
        #pragma unroll
        for (int pr = 0; pr < NPAIR; ++pr) {
            const int n0 = g * (2 * NPAIR) + 2 * pr;
            const float2 wa = W0[n0][ci];
            const float2 wb = W0[n0 + 1][ci];
            const float2 ra = Rs[n0];
            const float2 rb = Rs[n0 + 1];
            // seeds: x0 = Re(w), x1 = Re(w*r)
            const float x0a = wa.x;
            const float x0b = wb.x;
            const float x1a = wa.x * ra.x - wa.y * ra.y;
            const float x1b = wb.x * rb.x - wb.y * rb.y;
            // coeffs: p = 2 Re(r), q = -|r|^2
            const float pa = 2.0f * ra.x;
            const float pb = 2.0f * rb.x;
            const float qa = -(ra.x * ra.x + ra.y * ra.y);
            const float qb = -(rb.x * rb.x + rb.y * rb.y);
            PACK2(prev2[pr], x0a, x0b);
            PACK2(cur2[pr],  x1a, x1b);
            PACK2(p2[pr],    pa,  pb);
            PACK2(q2[pr],    qa,  qb);
        }
        // l = 0 contribution
        #pragma unroll
        for (int pr = 0; pr < NPAIR; ++pr)
            ADD2(acc2[0], acc2[0], prev2[pr]);
        // l = 1 .. LCc-1
        #pragma unroll
        for (int l = 1; l < LCc; ++l) {
            #pragma unroll
            for (int pr = 0; pr < NPAIR; ++pr) {
                ADD2(acc2[l], acc2[l], cur2[pr]);
                u64 t, nx;
                MUL2(t, q2[pr], prev2[pr]);          // q * x_{l-1}
                FMA2(nx, p2[pr], cur2[pr], t);       // x_{l+1} = p*x_l + q*x_{l-1}
                prev2[pr] = cur2[pr];
                cur2[pr]  = nx;
            }
        }
    }

    float* op = out + (size_t)h * L + l0;
    if (l0 + LCc <= L) {
        float res[LCc];
        #pragma unroll
        for (int l = 0; l < LCc; ++l) {
            unsigned int lo, hi;
            UNPACK2(lo, hi, acc2[l]);
            res[l] = 2.0f * (__uint_as_float(lo) + __uint_as_float(hi));
        }
        #pragma unroll
        for (int l = 0; l < LCc; l += 4) {
            *reinterpret_cast<float4*>(op + l) =
                make_float4(res[l], res[l + 1], res[l + 2], res[l + 3]);
        }
    } else {
        for (int l = 0; l < LCc && l0 + l < L; ++l) {
            unsigned int lo, hi;
            UNPACK2(lo, hi, acc2[l]);
            op[l] = 2.0f * (__uint_as_float(lo) + __uint_as_float(hi));
        }
    }
}

extern "C" void kernel_launch(void* const* d_in, const int* in_sizes, int n_in,
                              void* d_out, int out_size) {
    const float* C_real      = (const float*)d_in[0];
    const float* log_dt      = (const float*)d_in[1];
    const float* log_A_real  = (const float*)d_in[2];
    const float* A_imag      = (const float*)d_in[3];
    const float* omega_logit = (const float*)d_in[4];
    const float* eta_logit   = (const float*)d_in[5];
    float* out = (float*)d_out;

    const int L  = out_size / Hh;                 // CH == 1
    const int Lc = (L + LCc - 1) / LCc;           // total chunks
    const int gx = (Lc + CPBc - 1) / CPBc;        // blocks along l

    dim3 grid(gx, Hh);
    loong_spike_kernel<<<grid, 32>>>(C_real, log_dt, log_A_real, A_imag,
                                     omega_logit, eta_logit, out, L);
}